// round 1
// baseline (speedup 1.0000x reference)
#include <cuda_runtime.h>
#include <math.h>

// ---------------------------------------------------------------------------
// NNGAT_Net: B=512 graphs, N=200 nodes, INDIM=200.
// GAT1(200->32) -> topk(100) -> [bool augment-adj] -> GAT2(32->32) -> topk(50)
// -> readouts -> 3-layer MLP -> log_softmax.
// One CTA per batch element, 256 threads, everything staged in shared memory.
// Output layout: logp [512*2] | s1 [512*100] | s2 [512*50]  (77824 floats)
// ---------------------------------------------------------------------------

namespace {
constexpr int N_    = 200;
constexpr int IND   = 200;
constexpr int D1_   = 32;
constexpr int D2_   = 32;
constexpr int K1_   = 100;
constexpr int K2_   = 50;
constexpr int NT    = 256;          // threads per block (8 warps)
constexpr float NEGF = -1e9f;

// shared memory layout (in floats)
constexpr int OFF_W    = 0;         // 6400  W1 (phase A) / W2 (phase E, 1024)
constexpr int OFF_H    = 6400;      // 6400  h1 [200x32]; later h2 [100x32] @OFF_H, out2 @OFF_H+3200
constexpr int OFF_HO   = 12800;     // 6400  hout1 [200x32]
constexpr int OFF_XK   = 19200;     // 3200  xk [100x32]
constexpr int OFF_XK2  = 22400;     // 1600  xk2 [50x32]
constexpr int OFF_XT   = 24000;     // 1600  x tile [8x200]
constexpr int OFF_AL   = 25600;     // 1600  per-warp alpha rows [8x200]
constexpr int OFF_ES   = 27200;     // 256
constexpr int OFF_ED   = 27456;     // 256
constexpr int OFF_SC   = 27712;     // 256   scores
constexpr int OFF_VAL  = 27968;     // 128   topk vals
constexpr int OFF_PERM = 28096;     // 128   (int) topk1 perm
constexpr int OFF_PERM2= 28224;     // 64    (int) topk2 perm
constexpr int OFF_AKB  = 28288;     // 400   (u32) ak nonzero bitset [100][4]
constexpr int OFF_A2B  = 28688;     // 400   (u32) a2 nonzero bitset [100][4]
constexpr int OFF_Z    = 29088;     // 192   z[128], z1[32], z2[8], logits[2]
constexpr int OFF_RED  = 29280;     // 32    norms etc
constexpr int SMEM_FLOATS = 29312;  // 117248 bytes
}

__device__ __forceinline__ float warpMax(float v) {
    #pragma unroll
    for (int o = 16; o > 0; o >>= 1) v = fmaxf(v, __shfl_xor_sync(0xffffffffu, v, o));
    return v;
}
__device__ __forceinline__ float warpSum(float v) {
    #pragma unroll
    for (int o = 16; o > 0; o >>= 1) v += __shfl_xor_sync(0xffffffffu, v, o);
    return v;
}
__device__ __forceinline__ float lrelu02(float x) { return x > 0.f ? x : 0.2f * x; }

__global__ __launch_bounds__(NT, 1)
void nngat_kernel(
    const float* __restrict__ x,     const float* __restrict__ adj,
    const float* __restrict__ W1,    const float* __restrict__ a1s,
    const float* __restrict__ a1d,   const float* __restrict__ b1,
    const float* __restrict__ W2,    const float* __restrict__ a2s,
    const float* __restrict__ a2d,   const float* __restrict__ b2,
    const float* __restrict__ pw1,   const float* __restrict__ pw2,
    const float* __restrict__ fc1_w, const float* __restrict__ fc1_b,
    const float* __restrict__ fc2_w, const float* __restrict__ fc2_b,
    const float* __restrict__ fc3_w, const float* __restrict__ fc3_b,
    const float* __restrict__ bn4_g, const float* __restrict__ bn4_b,
    const float* __restrict__ bn5_g, const float* __restrict__ bn5_b,
    float* __restrict__ out)
{
    extern __shared__ float sm[];
    int*      smi  = (int*)sm;
    unsigned* smu  = (unsigned*)sm;

    const int b    = blockIdx.x;
    const int tid  = threadIdx.x;
    const int lane = tid & 31;
    const int wid  = tid >> 5;

    const float* xb   = x   + (size_t)b * N_ * IND;
    const float* adjb = adj + (size_t)b * N_ * N_;

    // ---- preload W1, norms of pw1/pw2 ----
    for (int t = tid; t < IND * D1_; t += NT) sm[OFF_W + t] = W1[t];
    if (wid == 0) {
        float v = pw1[lane];
        float s = warpSum(v * v);
        if (lane == 0) sm[OFF_RED + 0] = sqrtf(s) + 1e-16f;
    }
    if (wid == 1) {
        float v = pw2[lane];
        float s = warpSum(v * v);
        if (lane == 0) sm[OFF_RED + 1] = sqrtf(s) + 1e-16f;
    }
    __syncthreads();

    const float a1s_l = a1s[lane];
    const float a1d_l = a1d[lane];
    const float b1_l  = b1[lane];

    // ================= Phase A: h = x @ W1 ; es = h.a1s ; ed = h.a1d ========
    for (int i0 = 0; i0 < N_; i0 += 8) {
        // cooperative load of 8 contiguous rows of x
        for (int t = tid; t < 8 * IND; t += NT) sm[OFF_XT + t] = xb[i0 * IND + t];
        __syncthreads();

        const int i = i0 + wid;
        const float4* xr4 = (const float4*)(sm + OFF_XT + wid * IND);
        float acc0 = 0.f, acc1 = 0.f, acc2 = 0.f, acc3 = 0.f;
        #pragma unroll 4
        for (int k4 = 0; k4 < IND / 4; k4++) {
            float4 xv = xr4[k4];
            int k = k4 * 4;
            acc0 = fmaf(xv.x, sm[OFF_W + (k + 0) * D1_ + lane], acc0);
            acc1 = fmaf(xv.y, sm[OFF_W + (k + 1) * D1_ + lane], acc1);
            acc2 = fmaf(xv.z, sm[OFF_W + (k + 2) * D1_ + lane], acc2);
            acc3 = fmaf(xv.w, sm[OFF_W + (k + 3) * D1_ + lane], acc3);
        }
        float h = (acc0 + acc1) + (acc2 + acc3);
        sm[OFF_H + i * D1_ + lane] = h;
        float es = warpSum(h * a1s_l);
        float ed = warpSum(h * a1d_l);
        if (lane == 0) { sm[OFF_ES + i] = es; sm[OFF_ED + i] = ed; }
        __syncthreads();
    }

    // ================= Phase B: GAT1 attention softmax + aggregation ========
    for (int i0 = 0; i0 < N_; i0 += 8) {
        const int i = i0 + wid;
        const float edi = sm[OFF_ED + i];
        float* al = sm + OFF_AL + wid * N_;

        float mx = -INFINITY;
        for (int j = lane; j < N_; j += 32) {
            float w = adjb[i * N_ + j];
            bool msk = (w > 0.f) || (j == i);
            float lg = msk ? lrelu02(edi + sm[OFF_ES + j]) : NEGF;
            al[j] = lg;
            mx = fmaxf(mx, lg);
        }
        mx = warpMax(mx);
        float sme = 0.f;
        for (int j = lane; j < N_; j += 32) {
            float e = expf(al[j] - mx);
            al[j] = e;
            sme += e;
        }
        sme = warpSum(sme);
        const float inv = 1.f / sme;

        // aggregate: lane = feature dim
        const float4* al4 = (const float4*)al;
        float acc0 = 0.f, acc1 = 0.f, acc2 = 0.f, acc3 = 0.f;
        #pragma unroll 4
        for (int j4 = 0; j4 < N_ / 4; j4++) {
            float4 a = al4[j4];
            int j = j4 * 4;
            acc0 = fmaf(a.x, sm[OFF_H + (j + 0) * D1_ + lane], acc0);
            acc1 = fmaf(a.y, sm[OFF_H + (j + 1) * D1_ + lane], acc1);
            acc2 = fmaf(a.z, sm[OFF_H + (j + 2) * D1_ + lane], acc2);
            acc3 = fmaf(a.w, sm[OFF_H + (j + 3) * D1_ + lane], acc3);
        }
        sm[OFF_HO + i * D1_ + lane] = ((acc0 + acc1) + (acc2 + acc3)) * inv + b1_l;
    }
    __syncthreads();

    // ================= Phase C: top-k pool 1 ================================
    {
        const float pw1_l = pw1[lane];
        const float invn1 = 1.f / sm[OFF_RED + 0];
        for (int i0 = 0; i0 < N_; i0 += 8) {
            int i = i0 + wid;
            float s = warpSum(sm[OFF_HO + i * D1_ + lane] * pw1_l);
            if (lane == 0) sm[OFF_SC + i] = 1.f / (1.f + expf(-s * invn1));
        }
    }
    __syncthreads();

    // stable descending rank (ties: lower index first) == jax.lax.top_k order
    if (tid < N_) {
        float si = sm[OFF_SC + tid];
        int cnt = 0;
        for (int j = 0; j < N_; j++) {
            float sj = sm[OFF_SC + j];
            cnt += (sj > si) || (sj == si && j < tid);
        }
        if (cnt < K1_) smi[OFF_PERM + cnt] = tid;
    }
    __syncthreads();

    // s1 output + vals
    for (int r = tid; r < K1_; r += NT) {
        float v = sm[OFF_SC + smi[OFF_PERM + r]];
        sm[OFF_VAL + r] = v;
        out[512 * 2 + (size_t)b * K1_ + r] = v;
    }
    __syncthreads();

    // gated xk = hout[perm] * vals
    for (int t = tid; t < K1_ * D1_; t += NT) {
        int r = t >> 5, d = t & 31;
        sm[OFF_XK + t] = sm[OFF_HO + smi[OFF_PERM + r] * D1_ + d] * sm[OFF_VAL + r];
    }
    __syncthreads();

    // x1 = [max, mean] over kept nodes
    if (tid < 32) {
        float mx = -INFINITY, s = 0.f;
        for (int r = 0; r < K1_; r++) {
            float v = sm[OFF_XK + r * D1_ + tid];
            mx = fmaxf(mx, v);
            s += v;
        }
        sm[OFF_Z + tid]      = mx;
        sm[OFF_Z + 32 + tid] = s * (1.f / K1_);
    }

    // ak nonzero bitset: akb[r][w] bit t <-> adj[perm[r]][perm[w*32+t]] > 0
    for (int t = tid; t < K1_ * 4; t += NT) {
        int r = t >> 2, w = t & 3;
        int pr = smi[OFF_PERM + r];
        unsigned bits = 0;
        int cmax = min(w * 32 + 32, K1_);
        for (int c = w * 32; c < cmax; c++) {
            if (adjb[pr * N_ + smi[OFF_PERM + c]] > 0.f) bits |= 1u << (c - w * 32);
        }
        smu[OFF_AKB + t] = bits;
    }
    __syncthreads();

    // a2 nonzero bitset: a2 = (ak+I)(ak+I) off-diag != 0  <=>  ak | (ak_nz @ ak_nz)
    for (int t = tid; t < K1_ * 4; t += NT) {
        int r = t >> 2, w = t & 3;
        unsigned acc = smu[OFF_AKB + t];
        for (int k = 0; k < K1_; k++) {
            if ((smu[OFF_AKB + r * 4 + (k >> 5)] >> (k & 31)) & 1u)
                acc |= smu[OFF_AKB + k * 4 + w];
        }
        smu[OFF_A2B + t] = acc;
    }

    // ================= Phase E: GAT2 ========================================
    for (int t = tid; t < D1_ * D2_; t += NT) sm[OFF_W + t] = W2[t];
    __syncthreads();

    const float a2s_l = a2s[lane];
    const float a2d_l = a2d[lane];
    const float b2_l  = b2[lane];
    float* sH2   = sm + OFF_H;               // [100x32]
    float* sOUT2 = sm + OFF_H + K1_ * D2_;   // [100x32]

    for (int i0 = 0; i0 < K1_; i0 += 8) {
        int i = i0 + wid;
        if (i < K1_) {
            const float4* xr4 = (const float4*)(sm + OFF_XK + i * D1_);
            float acc = 0.f;
            #pragma unroll
            for (int k4 = 0; k4 < D1_ / 4; k4++) {
                float4 xv = xr4[k4];
                int k = k4 * 4;
                acc = fmaf(xv.x, sm[OFF_W + (k + 0) * D2_ + lane], acc);
                acc = fmaf(xv.y, sm[OFF_W + (k + 1) * D2_ + lane], acc);
                acc = fmaf(xv.z, sm[OFF_W + (k + 2) * D2_ + lane], acc);
                acc = fmaf(xv.w, sm[OFF_W + (k + 3) * D2_ + lane], acc);
            }
            sH2[i * D2_ + lane] = acc;
            float es = warpSum(acc * a2s_l);
            float ed = warpSum(acc * a2d_l);
            if (lane == 0) { sm[OFF_ES + i] = es; sm[OFF_ED + i] = ed; }
        }
    }
    __syncthreads();

    for (int i0 = 0; i0 < K1_; i0 += 8) {
        int i = i0 + wid;
        if (i < K1_) {
            const float edi = sm[OFF_ED + i];
            float* al = sm + OFF_AL + wid * N_;
            float mx = -INFINITY;
            for (int j = lane; j < K1_; j += 32) {
                bool msk = (j == i) || ((smu[OFF_A2B + i * 4 + (j >> 5)] >> (j & 31)) & 1u);
                float lg = msk ? lrelu02(edi + sm[OFF_ES + j]) : NEGF;
                al[j] = lg;
                mx = fmaxf(mx, lg);
            }
            mx = warpMax(mx);
            float sme = 0.f;
            for (int j = lane; j < K1_; j += 32) {
                float e = expf(al[j] - mx);
                al[j] = e;
                sme += e;
            }
            sme = warpSum(sme);
            const float inv = 1.f / sme;

            const float4* al4 = (const float4*)al;
            float acc0 = 0.f, acc1 = 0.f, acc2 = 0.f, acc3 = 0.f;
            #pragma unroll 5
            for (int j4 = 0; j4 < K1_ / 4; j4++) {
                float4 a = al4[j4];
                int j = j4 * 4;
                acc0 = fmaf(a.x, sH2[(j + 0) * D2_ + lane], acc0);
                acc1 = fmaf(a.y, sH2[(j + 1) * D2_ + lane], acc1);
                acc2 = fmaf(a.z, sH2[(j + 2) * D2_ + lane], acc2);
                acc3 = fmaf(a.w, sH2[(j + 3) * D2_ + lane], acc3);
            }
            sOUT2[i * D2_ + lane] = ((acc0 + acc1) + (acc2 + acc3)) * inv + b2_l;
        }
    }
    __syncthreads();

    // ================= Phase F: top-k pool 2 ================================
    {
        const float pw2_l = pw2[lane];
        const float invn2 = 1.f / sm[OFF_RED + 1];
        for (int i0 = 0; i0 < K1_; i0 += 8) {
            int i = i0 + wid;
            if (i < K1_) {
                float s = warpSum(sOUT2[i * D2_ + lane] * pw2_l);
                if (lane == 0) sm[OFF_SC + i] = 1.f / (1.f + expf(-s * invn2));
            }
        }
    }
    __syncthreads();

    if (tid < K1_) {
        float si = sm[OFF_SC + tid];
        int cnt = 0;
        for (int j = 0; j < K1_; j++) {
            float sj = sm[OFF_SC + j];
            cnt += (sj > si) || (sj == si && j < tid);
        }
        if (cnt < K2_) smi[OFF_PERM2 + cnt] = tid;
    }
    __syncthreads();

    for (int r = tid; r < K2_; r += NT) {
        float v = sm[OFF_SC + smi[OFF_PERM2 + r]];
        sm[OFF_VAL + r] = v;
        out[512 * 2 + 512 * K1_ + (size_t)b * K2_ + r] = v;
    }
    __syncthreads();

    for (int t = tid; t < K2_ * D2_; t += NT) {
        int r = t >> 5, d = t & 31;
        sm[OFF_XK2 + t] = sOUT2[smi[OFF_PERM2 + r] * D2_ + d] * sm[OFF_VAL + r];
    }
    __syncthreads();

    if (tid < 32) {
        float mx = -INFINITY, s = 0.f;
        for (int r = 0; r < K2_; r++) {
            float v = sm[OFF_XK2 + r * D2_ + tid];
            mx = fmaxf(mx, v);
            s += v;
        }
        sm[OFF_Z + 64 + tid] = mx;
        sm[OFF_Z + 96 + tid] = s * (1.f / K2_);
    }
    __syncthreads();

    // ================= Phase G: MLP head (warp 0) ===========================
    if (wid == 0) {
        const float invbn = 1.0f / sqrtf(1.0f + 1e-5f);
        // fc1: z[128] -> 32
        float acc = fc1_b[lane];
        #pragma unroll 4
        for (int k = 0; k < 128; k++) acc = fmaf(sm[OFF_Z + k], fc1_w[k * 32 + lane], acc);
        acc = fmaxf(acc, 0.f);
        sm[OFF_Z + 128 + lane] = bn4_g[lane] * acc * invbn + bn4_b[lane];
        __syncwarp();
        // fc2: 32 -> 8
        if (lane < 8) {
            float a = fc2_b[lane];
            #pragma unroll
            for (int k = 0; k < 32; k++) a = fmaf(sm[OFF_Z + 128 + k], fc2_w[k * 8 + lane], a);
            a = fmaxf(a, 0.f);
            sm[OFF_Z + 160 + lane] = bn5_g[lane] * a * invbn + bn5_b[lane];
        }
        __syncwarp();
        // fc3: 8 -> 2
        if (lane < 2) {
            float a = fc3_b[lane];
            #pragma unroll
            for (int k = 0; k < 8; k++) a = fmaf(sm[OFF_Z + 160 + k], fc3_w[k * 2 + lane], a);
            sm[OFF_Z + 170 + lane] = a;
        }
        __syncwarp();
        if (lane == 0) {
            float l0 = sm[OFF_Z + 170], l1 = sm[OFF_Z + 171];
            float m = fmaxf(l0, l1);
            float lse = m + logf(expf(l0 - m) + expf(l1 - m));
            out[(size_t)b * 2 + 0] = l0 - lse;
            out[(size_t)b * 2 + 1] = l1 - lse;
        }
    }
}

extern "C" void kernel_launch(void* const* d_in, const int* in_sizes, int n_in,
                              void* d_out, int out_size) {
    const float* x     = (const float*)d_in[0];
    const float* adj   = (const float*)d_in[1];
    const float* W1    = (const float*)d_in[2];
    const float* a1s   = (const float*)d_in[3];
    const float* a1d   = (const float*)d_in[4];
    const float* b1    = (const float*)d_in[5];
    const float* W2    = (const float*)d_in[6];
    const float* a2s   = (const float*)d_in[7];
    const float* a2d   = (const float*)d_in[8];
    const float* b2    = (const float*)d_in[9];
    const float* pw1   = (const float*)d_in[10];
    const float* pw2   = (const float*)d_in[11];
    const float* fc1w  = (const float*)d_in[12];
    const float* fc1b  = (const float*)d_in[13];
    const float* fc2w  = (const float*)d_in[14];
    const float* fc2b  = (const float*)d_in[15];
    const float* fc3w  = (const float*)d_in[16];
    const float* fc3b  = (const float*)d_in[17];
    const float* bn4g  = (const float*)d_in[18];
    const float* bn4b  = (const float*)d_in[19];
    const float* bn5g  = (const float*)d_in[20];
    const float* bn5b  = (const float*)d_in[21];
    float* out = (float*)d_out;

    const int smem_bytes = SMEM_FLOATS * (int)sizeof(float);
    cudaFuncSetAttribute(nngat_kernel, cudaFuncAttributeMaxDynamicSharedMemorySize,
                         smem_bytes);

    nngat_kernel<<<512, NT, smem_bytes>>>(
        x, adj, W1, a1s, a1d, b1, W2, a2s, a2d, b2, pw1, pw2,
        fc1w, fc1b, fc2w, fc2b, fc3w, fc3b, bn4g, bn4b, bn5g, bn5b, out);
}

// round 2
// speedup vs baseline: 2.9472x; 2.9472x over previous
#include <cuda_runtime.h>
#include <math.h>

// ---------------------------------------------------------------------------
// NNGAT_Net: B=512 graphs, N=200 nodes, INDIM=200.
// GAT1(200->32) -> topk(100) -> [bool augment-adj] -> GAT2(32->32) -> topk(50)
// -> readouts -> 3-layer MLP -> log_softmax.
// One CTA per batch, 256 threads, 96.3KB smem => 2 CTAs/SM.
// Sparse (bitset) GAT1 aggregation; adjacency bitset built via ballot.
// Output layout: logp [512*2] | s1 [512*100] | s2 [512*50]
// ---------------------------------------------------------------------------

namespace {
constexpr int N_    = 200;
constexpr int IND   = 200;
constexpr int D1_   = 32;
constexpr int D2_   = 32;
constexpr int K1_   = 100;
constexpr int K2_   = 50;
constexpr int NT    = 256;
constexpr float NEGF = -1e9f;

// shared memory layout (float indices)
constexpr int OFF_W     = 0;        // 6400: W1, later W2 (1024)
constexpr int OFF_H     = 6400;     // 6400: h1 [200x32]; later xk[100x32]@+0, xk2[50x32]@+3200
constexpr int OFF_HO    = 12800;    // 6400: hout1 [200x32]; later sH2[100x32]@+0, sOUT2@+3200
constexpr int OFF_AL    = 19200;    // 1600: per-warp alpha rows [8x200]
constexpr int OFF_ES    = 20800;    // 200
constexpr int OFF_ED    = 21000;    // 200
constexpr int OFF_SC    = 21200;    // 200
constexpr int OFF_VAL   = 21400;    // 100
constexpr int OFF_PERM  = 21500;    // 100 (int)
constexpr int OFF_PERM2 = 21600;    // 50  (int)
constexpr int OFF_ADJB  = 21652;    // 1400 (u32): full adj bitset [200][7]
constexpr int OFF_AKB   = 23052;    // 400 (u32): pooled adj bitset [100][4]
constexpr int OFF_A2B   = 23452;    // 400 (u32): augmented adj bitset [100][4]
constexpr int OFF_Z     = 23852;    // 192: z[128], z1[32], z2[8], logits
constexpr int OFF_RED   = 24044;    // 32
constexpr int SMEM_FLOATS = 24076;  // 96304 bytes
}

__device__ __forceinline__ float warpMax(float v) {
    #pragma unroll
    for (int o = 16; o > 0; o >>= 1) v = fmaxf(v, __shfl_xor_sync(0xffffffffu, v, o));
    return v;
}
__device__ __forceinline__ float warpSum(float v) {
    #pragma unroll
    for (int o = 16; o > 0; o >>= 1) v += __shfl_xor_sync(0xffffffffu, v, o);
    return v;
}
__device__ __forceinline__ float lrelu02(float x) { return x > 0.f ? x : 0.2f * x; }

__global__ __launch_bounds__(NT, 2)
void nngat_kernel(
    const float* __restrict__ x,     const float* __restrict__ adj,
    const float* __restrict__ W1,    const float* __restrict__ a1s,
    const float* __restrict__ a1d,   const float* __restrict__ b1,
    const float* __restrict__ W2,    const float* __restrict__ a2s,
    const float* __restrict__ a2d,   const float* __restrict__ b2,
    const float* __restrict__ pw1,   const float* __restrict__ pw2,
    const float* __restrict__ fc1_w, const float* __restrict__ fc1_b,
    const float* __restrict__ fc2_w, const float* __restrict__ fc2_b,
    const float* __restrict__ fc3_w, const float* __restrict__ fc3_b,
    const float* __restrict__ bn4_g, const float* __restrict__ bn4_b,
    const float* __restrict__ bn5_g, const float* __restrict__ bn5_b,
    float* __restrict__ out)
{
    extern __shared__ float sm[];
    int*      smi = (int*)sm;
    unsigned* smu = (unsigned*)sm;

    const int b    = blockIdx.x;
    const int tid  = threadIdx.x;
    const int lane = tid & 31;
    const int wid  = tid >> 5;

    const float* xb   = x   + (size_t)b * N_ * IND;
    const float* adjb = adj + (size_t)b * N_ * N_;

    // ---- preload W1, norms of pw1/pw2 ----
    for (int t = tid; t < IND * D1_; t += NT) sm[OFF_W + t] = W1[t];
    if (wid == 0) {
        float v = pw1[lane];
        float s = warpSum(v * v);
        if (lane == 0) sm[OFF_RED + 0] = sqrtf(s) + 1e-16f;
    }
    if (wid == 1) {
        float v = pw2[lane];
        float s = warpSum(v * v);
        if (lane == 0) sm[OFF_RED + 1] = sqrtf(s) + 1e-16f;
    }
    __syncthreads();

    const float a1s_l = a1s[lane];
    const float a1d_l = a1d[lane];
    const float b1_l  = b1[lane];

    // ============ Phase A: h = x @ W1 ; es = h.a1s ; ed = h.a1d =============
    // Each warp owns rows [wid*25, wid*25+25), processed 5 at a time so each
    // W-column LDS is reused across 5 rows (20 independent FMA chains).
    {
        const int rbase = wid * 25;
        #pragma unroll
        for (int g = 0; g < 5; g++) {
            const int ib = rbase + g * 5;
            const float4* xp0 = (const float4*)(xb + (ib + 0) * IND);
            const float4* xp1 = (const float4*)(xb + (ib + 1) * IND);
            const float4* xp2 = (const float4*)(xb + (ib + 2) * IND);
            const float4* xp3 = (const float4*)(xb + (ib + 3) * IND);
            const float4* xp4 = (const float4*)(xb + (ib + 4) * IND);
            float a0 = 0.f, a1 = 0.f, a2 = 0.f, a3 = 0.f, a4 = 0.f;
            #pragma unroll 2
            for (int k4 = 0; k4 < IND / 4; k4++) {
                float4 v0 = __ldg(xp0 + k4);
                float4 v1 = __ldg(xp1 + k4);
                float4 v2 = __ldg(xp2 + k4);
                float4 v3 = __ldg(xp3 + k4);
                float4 v4 = __ldg(xp4 + k4);
                const int k = k4 * 4;
                float w0 = sm[OFF_W + (k + 0) * D1_ + lane];
                float w1 = sm[OFF_W + (k + 1) * D1_ + lane];
                float w2 = sm[OFF_W + (k + 2) * D1_ + lane];
                float w3 = sm[OFF_W + (k + 3) * D1_ + lane];
                a0 = fmaf(v0.x, w0, fmaf(v0.y, w1, fmaf(v0.z, w2, fmaf(v0.w, w3, a0))));
                a1 = fmaf(v1.x, w0, fmaf(v1.y, w1, fmaf(v1.z, w2, fmaf(v1.w, w3, a1))));
                a2 = fmaf(v2.x, w0, fmaf(v2.y, w1, fmaf(v2.z, w2, fmaf(v2.w, w3, a2))));
                a3 = fmaf(v3.x, w0, fmaf(v3.y, w1, fmaf(v3.z, w2, fmaf(v3.w, w3, a3))));
                a4 = fmaf(v4.x, w0, fmaf(v4.y, w1, fmaf(v4.z, w2, fmaf(v4.w, w3, a4))));
            }
            float hr[5] = {a0, a1, a2, a3, a4};
            #pragma unroll
            for (int r = 0; r < 5; r++) {
                sm[OFF_H + (ib + r) * D1_ + lane] = hr[r];
                float es = warpSum(hr[r] * a1s_l);
                float ed = warpSum(hr[r] * a1d_l);
                if (lane == 0) { sm[OFF_ES + ib + r] = es; sm[OFF_ED + ib + r] = ed; }
            }
        }
    }
    __syncthreads();

    // ============ Phase B: GAT1 softmax + SPARSE aggregation ================
    for (int i0 = 0; i0 < N_; i0 += 8) {
        const int i = i0 + wid;
        const float edi = sm[OFF_ED + i];
        float* al = sm + OFF_AL + wid * N_;

        unsigned mw[7];
        float mx = -INFINITY;
        #pragma unroll
        for (int c = 0; c < 7; c++) {
            const int j = c * 32 + lane;
            float w = (j < N_) ? adjb[i * N_ + j] : 0.f;
            unsigned bal = __ballot_sync(0xffffffffu, w > 0.f);
            if (lane == 0) smu[OFF_ADJB + i * 7 + c] = bal;   // pure adjacency bitset
            if ((i >> 5) == c) bal |= 1u << (i & 31);         // add self-loop
            mw[c] = bal;
            if ((bal >> lane) & 1u) {
                float lg = lrelu02(edi + sm[OFF_ES + j]);
                al[j] = lg;
                mx = fmaxf(mx, lg);
            }
        }
        mx = warpMax(mx);

        float s = 0.f;
        #pragma unroll
        for (int c = 0; c < 7; c++) {
            if ((mw[c] >> lane) & 1u) {
                const int j = c * 32 + lane;
                float e = __expf(al[j] - mx);
                al[j] = e;
                s += e;
            }
        }
        s = warpSum(s);
        const float inv = 1.f / s;

        float acc = 0.f;
        #pragma unroll
        for (int c = 0; c < 7; c++) {
            unsigned w = mw[c];
            while (w) {
                const int t = __ffs(w) - 1;
                w &= w - 1;
                const int j = c * 32 + t;
                acc = fmaf(al[j], sm[OFF_H + j * D1_ + lane], acc);
            }
        }
        sm[OFF_HO + i * D1_ + lane] = acc * inv + b1_l;
    }
    __syncthreads();

    // ============ Phase C: pool-1 scores; load W2 ============================
    {
        const float pw1_l = pw1[lane];
        const float invn1 = 1.f / sm[OFF_RED + 0];
        for (int i0 = 0; i0 < N_; i0 += 8) {
            const int i = i0 + wid;
            float s = warpSum(sm[OFF_HO + i * D1_ + lane] * pw1_l);
            if (lane == 0) sm[OFF_SC + i] = 1.f / (1.f + __expf(-s * invn1));
        }
    }
    for (int t = tid; t < D1_ * D2_; t += NT) sm[OFF_W + t] = W2[t];  // W1 dead
    __syncthreads();

    // stable descending rank (ties: lower index first) == jax.lax.top_k order
    if (tid < N_) {
        const float si = sm[OFF_SC + tid];
        int cnt = 0;
        for (int j = 0; j < N_; j++) {
            const float sj = sm[OFF_SC + j];
            cnt += (sj > si) || (sj == si && j < tid);
        }
        if (cnt < K1_) smi[OFF_PERM + cnt] = tid;
    }
    __syncthreads();

    for (int r = tid; r < K1_; r += NT) {
        float v = sm[OFF_SC + smi[OFF_PERM + r]];
        sm[OFF_VAL + r] = v;
        out[512 * 2 + (size_t)b * K1_ + r] = v;
    }
    __syncthreads();

    // gated xk = hout[perm] * vals   (into the dead h1 region)
    for (int t = tid; t < K1_ * D1_; t += NT) {
        const int r = t >> 5, d = t & 31;
        sm[OFF_H + t] = sm[OFF_HO + smi[OFF_PERM + r] * D1_ + d] * sm[OFF_VAL + r];
    }
    __syncthreads();

    // x1 readout (warp0) + AKB build from the smem adjacency bitset
    if (tid < 32) {
        float mx = -INFINITY, s = 0.f;
        for (int r = 0; r < K1_; r++) {
            float v = sm[OFF_H + r * D1_ + tid];
            mx = fmaxf(mx, v);
            s += v;
        }
        sm[OFF_Z + tid]      = mx;
        sm[OFF_Z + 32 + tid] = s * (1.f / K1_);
    }
    for (int t = tid; t < K1_ * 4; t += NT) {
        const int r = t >> 2, w = t & 3;
        const int pr = smi[OFF_PERM + r];
        unsigned bits = 0;
        const int cmax = min(w * 32 + 32, K1_);
        for (int c = w * 32; c < cmax; c++) {
            const int pc = smi[OFF_PERM + c];
            if ((smu[OFF_ADJB + pr * 7 + (pc >> 5)] >> (pc & 31)) & 1u)
                bits |= 1u << (c - w * 32);
        }
        smu[OFF_AKB + t] = bits;
    }
    __syncthreads();

    // a2 nonzero bitset: ak | (ak_nz @ ak_nz)  (bool matmul over bitsets)
    for (int t = tid; t < K1_ * 4; t += NT) {
        const int r = t >> 2, w = t & 3;
        unsigned acc = smu[OFF_AKB + t];
        for (int k = 0; k < K1_; k++) {
            if ((smu[OFF_AKB + r * 4 + (k >> 5)] >> (k & 31)) & 1u)
                acc |= smu[OFF_AKB + k * 4 + w];
        }
        smu[OFF_A2B + t] = acc;
    }
    __syncthreads();

    // ============ Phase E: GAT2 =============================================
    const float a2s_l = a2s[lane];
    const float a2d_l = a2d[lane];
    const float b2_l  = b2[lane];
    float* sXK   = sm + OFF_H;                 // [100x32] pooled features
    float* sH2   = sm + OFF_HO;                // [100x32]
    float* sOUT2 = sm + OFF_HO + K1_ * D2_;    // [100x32]

    for (int i0 = 0; i0 < K1_; i0 += 8) {
        const int i = i0 + wid;
        if (i < K1_) {
            const float4* xr4 = (const float4*)(sXK + i * D1_);
            float acc = 0.f;
            #pragma unroll
            for (int k4 = 0; k4 < D1_ / 4; k4++) {
                float4 xv = xr4[k4];
                const int k = k4 * 4;
                acc = fmaf(xv.x, sm[OFF_W + (k + 0) * D2_ + lane], acc);
                acc = fmaf(xv.y, sm[OFF_W + (k + 1) * D2_ + lane], acc);
                acc = fmaf(xv.z, sm[OFF_W + (k + 2) * D2_ + lane], acc);
                acc = fmaf(xv.w, sm[OFF_W + (k + 3) * D2_ + lane], acc);
            }
            sH2[i * D2_ + lane] = acc;
            float es = warpSum(acc * a2s_l);
            float ed = warpSum(acc * a2d_l);
            if (lane == 0) { sm[OFF_ES + i] = es; sm[OFF_ED + i] = ed; }
        }
    }
    __syncthreads();

    for (int i0 = 0; i0 < K1_; i0 += 8) {
        const int i = i0 + wid;
        if (i < K1_) {
            const float edi = sm[OFF_ED + i];
            float* al = sm + OFF_AL + wid * N_;
            float mx = -INFINITY;
            #pragma unroll
            for (int c = 0; c < 4; c++) {
                const int j = c * 32 + lane;
                if (j < K1_) {
                    bool msk = (j == i) || ((smu[OFF_A2B + i * 4 + c] >> lane) & 1u);
                    float lg = msk ? lrelu02(edi + sm[OFF_ES + j]) : NEGF;
                    al[j] = lg;
                    mx = fmaxf(mx, lg);
                }
            }
            mx = warpMax(mx);
            float sme = 0.f;
            #pragma unroll
            for (int c = 0; c < 4; c++) {
                const int j = c * 32 + lane;
                if (j < K1_) {
                    float e = __expf(al[j] - mx);
                    al[j] = e;
                    sme += e;
                }
            }
            sme = warpSum(sme);
            const float inv = 1.f / sme;

            const float4* al4 = (const float4*)al;
            float acc0 = 0.f, acc1 = 0.f, acc2 = 0.f, acc3 = 0.f;
            #pragma unroll 5
            for (int j4 = 0; j4 < K1_ / 4; j4++) {
                float4 a = al4[j4];
                const int j = j4 * 4;
                acc0 = fmaf(a.x, sH2[(j + 0) * D2_ + lane], acc0);
                acc1 = fmaf(a.y, sH2[(j + 1) * D2_ + lane], acc1);
                acc2 = fmaf(a.z, sH2[(j + 2) * D2_ + lane], acc2);
                acc3 = fmaf(a.w, sH2[(j + 3) * D2_ + lane], acc3);
            }
            sOUT2[i * D2_ + lane] = ((acc0 + acc1) + (acc2 + acc3)) * inv + b2_l;
        }
    }
    __syncthreads();

    // ============ Phase F: pool-2 ===========================================
    {
        const float pw2_l = pw2[lane];
        const float invn2 = 1.f / sm[OFF_RED + 1];
        for (int i0 = 0; i0 < K1_; i0 += 8) {
            const int i = i0 + wid;
            if (i < K1_) {
                float s = warpSum(sOUT2[i * D2_ + lane] * pw2_l);
                if (lane == 0) sm[OFF_SC + i] = 1.f / (1.f + __expf(-s * invn2));
            }
        }
    }
    __syncthreads();

    if (tid < K1_) {
        const float si = sm[OFF_SC + tid];
        int cnt = 0;
        for (int j = 0; j < K1_; j++) {
            const float sj = sm[OFF_SC + j];
            cnt += (sj > si) || (sj == si && j < tid);
        }
        if (cnt < K2_) smi[OFF_PERM2 + cnt] = tid;
    }
    __syncthreads();

    for (int r = tid; r < K2_; r += NT) {
        float v = sm[OFF_SC + smi[OFF_PERM2 + r]];
        sm[OFF_VAL + r] = v;
        out[512 * 2 + 512 * K1_ + (size_t)b * K2_ + r] = v;
    }
    __syncthreads();

    float* sXK2 = sm + OFF_H + K1_ * D1_;   // [50x32], after xk in the H region
    for (int t = tid; t < K2_ * D2_; t += NT) {
        const int r = t >> 5, d = t & 31;
        sXK2[t] = sOUT2[smi[OFF_PERM2 + r] * D2_ + d] * sm[OFF_VAL + r];
    }
    __syncthreads();

    if (tid < 32) {
        float mx = -INFINITY, s = 0.f;
        for (int r = 0; r < K2_; r++) {
            float v = sXK2[r * D2_ + tid];
            mx = fmaxf(mx, v);
            s += v;
        }
        sm[OFF_Z + 64 + tid] = mx;
        sm[OFF_Z + 96 + tid] = s * (1.f / K2_);
    }
    __syncthreads();

    // ============ Phase G: MLP head (warp 0) ================================
    if (wid == 0) {
        const float invbn = 1.0f / sqrtf(1.0f + 1e-5f);
        float acc = fc1_b[lane];
        #pragma unroll 4
        for (int k = 0; k < 128; k++) acc = fmaf(sm[OFF_Z + k], __ldg(&fc1_w[k * 32 + lane]), acc);
        acc = fmaxf(acc, 0.f);
        sm[OFF_Z + 128 + lane] = bn4_g[lane] * acc * invbn + bn4_b[lane];
        __syncwarp();
        if (lane < 8) {
            float a = fc2_b[lane];
            #pragma unroll
            for (int k = 0; k < 32; k++) a = fmaf(sm[OFF_Z + 128 + k], __ldg(&fc2_w[k * 8 + lane]), a);
            a = fmaxf(a, 0.f);
            sm[OFF_Z + 160 + lane] = bn5_g[lane] * a * invbn + bn5_b[lane];
        }
        __syncwarp();
        if (lane < 2) {
            float a = fc3_b[lane];
            #pragma unroll
            for (int k = 0; k < 8; k++) a = fmaf(sm[OFF_Z + 160 + k], __ldg(&fc3_w[k * 2 + lane]), a);
            sm[OFF_Z + 170 + lane] = a;
        }
        __syncwarp();
        if (lane == 0) {
            float l0 = sm[OFF_Z + 170], l1 = sm[OFF_Z + 171];
            float m = fmaxf(l0, l1);
            float lse = m + __logf(__expf(l0 - m) + __expf(l1 - m));
            out[(size_t)b * 2 + 0] = l0 - lse;
            out[(size_t)b * 2 + 1] = l1 - lse;
        }
    }
}

extern "C" void kernel_launch(void* const* d_in, const int* in_sizes, int n_in,
                              void* d_out, int out_size) {
    const float* x     = (const float*)d_in[0];
    const float* adj   = (const float*)d_in[1];
    const float* W1    = (const float*)d_in[2];
    const float* a1s   = (const float*)d_in[3];
    const float* a1d   = (const float*)d_in[4];
    const float* b1    = (const float*)d_in[5];
    const float* W2    = (const float*)d_in[6];
    const float* a2s   = (const float*)d_in[7];
    const float* a2d   = (const float*)d_in[8];
    const float* b2    = (const float*)d_in[9];
    const float* pw1   = (const float*)d_in[10];
    const float* pw2   = (const float*)d_in[11];
    const float* fc1w  = (const float*)d_in[12];
    const float* fc1b  = (const float*)d_in[13];
    const float* fc2w  = (const float*)d_in[14];
    const float* fc2b  = (const float*)d_in[15];
    const float* fc3w  = (const float*)d_in[16];
    const float* fc3b  = (const float*)d_in[17];
    const float* bn4g  = (const float*)d_in[18];
    const float* bn4b  = (const float*)d_in[19];
    const float* bn5g  = (const float*)d_in[20];
    const float* bn5b  = (const float*)d_in[21];
    float* out = (float*)d_out;

    const int smem_bytes = SMEM_FLOATS * (int)sizeof(float);
    cudaFuncSetAttribute(nngat_kernel, cudaFuncAttributeMaxDynamicSharedMemorySize,
                         smem_bytes);

    nngat_kernel<<<512, NT, smem_bytes>>>(
        x, adj, W1, a1s, a1d, b1, W2, a2s, a2d, b2, pw1, pw2,
        fc1w, fc1b, fc2w, fc2b, fc3w, fc3b, bn4g, bn4b, bn5g, bn5b, out);
}